// round 14
// baseline (speedup 1.0000x reference)
#include <cuda_runtime.h>
#include <stdint.h>
#include <math.h>

#define Bdim 4
#define Ndim 2048
#define Ddim 1024
#define Hdim 8
#define Edim 16
#define CSdim 2048
#define Rdim (Bdim*Ndim)   /* 8192 rows */
#define Jdim (Hdim*Edim)   /* 128 projection outputs per row */

// Borderline threshold: flag (row,head) where top-2 gap <= TAU * ||y||.
// Observed flip scale ~5e-6*||y||; 3e-5 keeps >=6x margin, cnt ~3x lower than 1e-4.
#define TAU 3e-5f

// ---------------- device scratch (no allocations allowed) ----------------
__device__ float  g_Wt[Ddim*Jdim];            // transposed projs [d][j]  (512KB)
__device__ float  g_WtT[Jdim*Ddim];           // column-major projs [j][d] (512KB, for kFix)
__device__ float  g_cb4[Hdim*CSdim*Edim];     // fp32 normalized codebook, 4-code interleaved (512KB)
__device__ double g_cbd[Hdim*CSdim*Edim];     // fp64 normalized codebook [h][c][e] (2MB)
__device__ float  g_Y[Rdim*Jdim];             // projections after mean-subtract (4MB)
__device__ int    g_list[Rdim*Hdim];          // compact worklist of borderline cases
__device__ int    g_cnt;                      // worklist counter

typedef unsigned long long u64;

__device__ __forceinline__ u64 pack2(float lo, float hi) {
    u64 r; asm("mov.b64 %0,{%1,%2};" : "=l"(r) : "f"(lo), "f"(hi)); return r;
}
__device__ __forceinline__ void unpack2(float& lo, float& hi, u64 v) {
    asm("mov.b64 {%0,%1},%2;" : "=f"(lo), "=f"(hi) : "l"(v));
}
__device__ __forceinline__ u64 ffma2(u64 a, u64 b, u64 c) {
    u64 d; asm("fma.rn.f32x2 %0,%1,%2,%3;" : "=l"(d) : "l"(a), "l"(b), "l"(c)); return d;
}
__device__ __forceinline__ u64 fadd2(u64 a, u64 b) {
    u64 d; asm("add.rn.f32x2 %0,%1,%2;" : "=l"(d) : "l"(a), "l"(b)); return d;
}
__device__ __forceinline__ bool betterf(float av, int ai, float bv, int bi) {
    return (av > bv) || (av == bv && ai < bi);
}

// ---------------- prep A: transposes of W + codebook normalize (fp32 & fp64) --
__global__ void kPrepA(const float* __restrict__ W, const float* __restrict__ cbk) {
    if (blockIdx.x == 0 && threadIdx.x == 0) g_cnt = 0;
    if (blockIdx.x < 512) {
        int idx = blockIdx.x * 256 + threadIdx.x;
        int d = idx >> 7, j = idx & 127;
        float v = W[(j >> 4) * (Ddim * Edim) + d * Edim + (j & 15)];
        g_Wt[idx] = v;
        g_WtT[j * Ddim + d] = v;
    } else {
        int idx = (blockIdx.x - 512) * 256 + threadIdx.x;
        const float* row = cbk + (size_t)idx * Edim;
        float v[Edim];
        double ss = 0.0;
#pragma unroll
        for (int e = 0; e < Edim; e++) { v[e] = row[e]; ss += (double)v[e] * (double)v[e]; }
        double invd = 1.0 / sqrt(ss + 1e-12);
        float inv = (float)invd;
        int h = idx >> 11, c = idx & 2047;
        float* dst = g_cb4 + (size_t)h * (CSdim * Edim) + (c >> 2) * 64 + (c & 3);
        double* dd = g_cbd + (size_t)idx * Edim;
#pragma unroll
        for (int e = 0; e < Edim; e++) {
            dst[e * 4] = v[e] * inv;
            dd[e] = (double)v[e] * invd;
        }
    }
}

// ---------------- kernel Y: Y = X @ Wt - mu * S (64x128 tile, dbl-buffered) ---
__global__ __launch_bounds__(256) void kernY(const float* __restrict__ x) {
    __shared__ __align__(16) float Xs[16][68];
    __shared__ __align__(16) float Wsm[16][128];
    __shared__ float Ssm[128];
    __shared__ float redsum[256];
    __shared__ float mus[64];

    int tid = threadIdx.x;
    int row0 = blockIdx.x * 64;

    int tx = tid & 15, ty = tid >> 4;
    int ldr = tid >> 2, ldc = (tid & 3) * 4;
    int wr  = tid >> 4, wc  = (tid & 15) * 8;

    u64 acc[4][4];
#pragma unroll
    for (int i = 0; i < 4; i++)
#pragma unroll
        for (int p = 0; p < 4; p++) acc[i][p] = 0ull;

    float psum = 0.f;
    float s8[8] = {0.f,0.f,0.f,0.f,0.f,0.f,0.f,0.f};

    float4 xv  = *(const float4*)(x + (size_t)(row0 + ldr) * Ddim + ldc);
    float4 wv0 = *(const float4*)(g_Wt + (size_t)wr * Jdim + wc);
    float4 wv1 = *(const float4*)(g_Wt + (size_t)wr * Jdim + wc + 4);

    for (int kc = 0; kc < Ddim / 16; kc++) {
        psum += xv.x + xv.y + xv.z + xv.w;
        s8[0] += wv0.x; s8[1] += wv0.y; s8[2] += wv0.z; s8[3] += wv0.w;
        s8[4] += wv1.x; s8[5] += wv1.y; s8[6] += wv1.z; s8[7] += wv1.w;
        Xs[ldc + 0][ldr] = xv.x;
        Xs[ldc + 1][ldr] = xv.y;
        Xs[ldc + 2][ldr] = xv.z;
        Xs[ldc + 3][ldr] = xv.w;
        *(float4*)&Wsm[wr][wc]     = wv0;
        *(float4*)&Wsm[wr][wc + 4] = wv1;
        __syncthreads();

        float4 nxv = xv, nwv0 = wv0, nwv1 = wv1;
        if (kc < Ddim / 16 - 1) {
            int k0 = (kc + 1) * 16;
            nxv  = *(const float4*)(x + (size_t)(row0 + ldr) * Ddim + k0 + ldc);
            nwv0 = *(const float4*)(g_Wt + (size_t)(k0 + wr) * Jdim + wc);
            nwv1 = *(const float4*)(g_Wt + (size_t)(k0 + wr) * Jdim + wc + 4);
        }

#pragma unroll
        for (int k = 0; k < 16; k++) {
            float4 av = *(const float4*)&Xs[k][ty * 4];
            u64 a0 = pack2(av.x, av.x);
            u64 a1 = pack2(av.y, av.y);
            u64 a2 = pack2(av.z, av.z);
            u64 a3 = pack2(av.w, av.w);
#pragma unroll
            for (int p = 0; p < 4; p++) {
                u64 b = *(const u64*)&Wsm[k][p * 32 + tx * 2];
                acc[0][p] = ffma2(a0, b, acc[0][p]);
                acc[1][p] = ffma2(a1, b, acc[1][p]);
                acc[2][p] = ffma2(a2, b, acc[2][p]);
                acc[3][p] = ffma2(a3, b, acc[3][p]);
            }
        }
        __syncthreads();
        xv = nxv; wv0 = nwv0; wv1 = nwv1;
    }

    redsum[tid] = psum;
#pragma unroll
    for (int i = 0; i < 4; i++) Wsm[wr][wc + i]     = s8[i];
#pragma unroll
    for (int i = 0; i < 4; i++) Wsm[wr][wc + 4 + i] = s8[4 + i];
    __syncthreads();
    if (tid < 64)
        mus[tid] = (redsum[4 * tid] + redsum[4 * tid + 1] +
                    redsum[4 * tid + 2] + redsum[4 * tid + 3]) * (1.0f / Ddim);
    if (tid < 128) {
        float t = 0.f;
#pragma unroll
        for (int r16 = 0; r16 < 16; r16++) t += Wsm[r16][tid];
        Ssm[tid] = t;
    }
    __syncthreads();

#pragma unroll
    for (int i = 0; i < 4; i++) {
        int r = row0 + ty * 4 + i;
        float mu = mus[ty * 4 + i];
#pragma unroll
        for (int p = 0; p < 4; p++) {
            int n0 = p * 32 + tx * 2;
            float lo, hi;
            unpack2(lo, hi, acc[i][p]);
            lo -= mu * Ssm[n0];
            hi -= mu * Ssm[n0 + 1];
            *(float2*)(g_Y + (size_t)r * Jdim + n0) = make_float2(lo, hi);
        }
    }
}

// ---------------- kernel S: FFMA2 sims, 1 row/lane, 32-row CTA, 3 CTAs/SM -----
// CTA = 32 rows x 1 head, 8 warps; lane = row, warp = code subset (8 quads/chunk).
// ~80 regs -> 3 CTAs/SM (occ 2x prior) to lift issue efficiency.
__global__ __launch_bounds__(256, 3) void kernS(float* __restrict__ out) {
    __shared__ __align__(16) float buf[2][4096];   // 2 x 16KB chunks
    __shared__ float sv1[8][32];
    __shared__ float sv2[8][32];
    __shared__ int   six[8][32];

    int tid = threadIdx.x;
    int lane = tid & 31, warp = tid >> 5;
    int h = blockIdx.y;
    int r = blockIdx.x * 32 + lane;        // this lane's row

    // y (this row) duplicated into f32x2 registers
    u64 y2[Edim];
    float ynorm;
    {
        const float* yp = g_Y + (size_t)r * Jdim + h * Edim;
        float n2 = 0.f;
#pragma unroll
        for (int e4 = 0; e4 < 4; e4++) {
            float4 v = *(const float4*)(yp + e4 * 4);
            n2 += v.x*v.x + v.y*v.y + v.z*v.z + v.w*v.w;
            y2[e4 * 4 + 0] = pack2(v.x, v.x);
            y2[e4 * 4 + 1] = pack2(v.y, v.y);
            y2[e4 * 4 + 2] = pack2(v.z, v.z);
            y2[e4 * 4 + 3] = pack2(v.w, v.w);
        }
        ynorm = sqrtf(n2);
    }

    const float NEGINF = __int_as_float(0xff800000u);
    float v1 = NEGINF, v2 = NEGINF;
    int bi = 0;

    const float4* src = (const float4*)(g_cb4 + (size_t)h * (CSdim * Edim));

    // preload chunk 0 (256 codes = 1024 float4)
#pragma unroll
    for (int i = 0; i < 4; i++)
        ((float4*)buf[0])[tid + 256 * i] = src[tid + 256 * i];
    __syncthreads();

    for (int ch = 0; ch < 8; ch++) {
        int pb = ch & 1;
        float4 pf0, pf1, pf2, pf3;
        if (ch < 7) {
            const float4* s2 = src + (ch + 1) * 1024;
            pf0 = s2[tid];       pf1 = s2[tid + 256];
            pf2 = s2[tid + 512]; pf3 = s2[tid + 768];
        }

        const float* cbp = buf[pb] + warp * (8 * 64);   // this warp's 8 quad-groups
        int cbase = (ch * 64 + warp * 8) * 4;           // first code index

#pragma unroll 2
        for (int t = 0; t < 8; t++) {
            u64 aA = 0ull, aB = 0ull, bA = 0ull, bB = 0ull;   // 4 chains
            const float* cq = cbp + t * 64;
#pragma unroll
            for (int e = 0; e < 8; e++) {
                longlong2 bb = *(const longlong2*)(cq + e * 4);  // LDS128 broadcast
                aA = ffma2(y2[e], (u64)bb.x, aA);
                aB = ffma2(y2[e], (u64)bb.y, aB);
            }
#pragma unroll
            for (int e = 8; e < 16; e++) {
                longlong2 bb = *(const longlong2*)(cq + e * 4);
                bA = ffma2(y2[e], (u64)bb.x, bA);
                bB = ffma2(y2[e], (u64)bb.y, bB);
            }
            u64 sAB = fadd2(aA, bA), sCD = fadd2(aB, bB);
            int c0 = cbase + t * 4;
            float s0, s1, s2, s3, m;
            unpack2(s0, s1, sAB); unpack2(s2, s3, sCD);
            bi = (s0 > v1) ? c0     : bi; m = fminf(v1, s0); v1 = fmaxf(v1, s0); v2 = fmaxf(v2, m);
            bi = (s1 > v1) ? c0 + 1 : bi; m = fminf(v1, s1); v1 = fmaxf(v1, s1); v2 = fmaxf(v2, m);
            bi = (s2 > v1) ? c0 + 2 : bi; m = fminf(v1, s2); v1 = fmaxf(v1, s2); v2 = fmaxf(v2, m);
            bi = (s3 > v1) ? c0 + 3 : bi; m = fminf(v1, s3); v1 = fmaxf(v1, s3); v2 = fmaxf(v2, m);
        }

        __syncthreads();
        if (ch < 7) {
            float4* d2 = (float4*)buf[pb ^ 1];
            d2[tid] = pf0;       d2[tid + 256] = pf1;
            d2[tid + 512] = pf2; d2[tid + 768] = pf3;
            __syncthreads();
        }
    }

    sv1[warp][lane] = v1;
    sv2[warp][lane] = v2;
    six[warp][lane] = bi;
    __syncthreads();

    if (warp == 0) {
        float w1 = NEGINF, w2 = NEGINF;
        int i1 = 0;
#pragma unroll
        for (int w = 0; w < 8; w++) {
            float a = sv1[w][lane];
            int  ia = six[w][lane];
            float b = sv2[w][lane];
            if (a > w1 || (a == w1 && ia < i1)) {
                w2 = fmaxf(w2, w1); w1 = a; i1 = ia;
            } else {
                w2 = fmaxf(w2, a);
            }
            w2 = fmaxf(w2, b);
        }
        int id = r * Hdim + h;
        out[id] = (float)i1;
        if (w1 - w2 <= TAU * ynorm) {
            int slot = atomicAdd(&g_cnt, 1);
            g_list[slot] = id;
        }
    }
}

// ---------------- kernel Fix: candidate top-2 (fp32) + fp64 verdict -----------
__global__ __launch_bounds__(256) void kFix(const float* __restrict__ x,
                                            float* __restrict__ out) {
    __shared__ float  syf[Edim];
    __shared__ float  wv1s[8], wv2s[8];
    __shared__ int    wi1s[8], wi2s[8];
    __shared__ double redd[256];
    __shared__ double spd[Edim];
    __shared__ int    cands[2];

    int tid = threadIdx.x;
    int lane = tid & 31, warp = tid >> 5;
    int cnt = g_cnt;

    for (int item = blockIdx.x; item < cnt; item += 2048) {
        int wid = g_list[item];
        int row = wid >> 3, h = wid & 7;

        // ---- PA: fp32 re-rank from g_Y -> top-2 candidate codes ----
        if (tid < Edim) syf[tid] = g_Y[(size_t)row * Jdim + h * Edim + tid];
        __syncthreads();
        float yv[Edim];
#pragma unroll
        for (int e = 0; e < Edim; e++) yv[e] = syf[e];

        const float* cbh = g_cb4 + (size_t)h * (CSdim * Edim);
        const float NEGINF = __int_as_float(0xff800000u);
        float v1 = NEGINF, v2 = NEGINF;
        int i1 = 0, i2 = 1;
#pragma unroll
        for (int j = 0; j < 8; j++) {
            int c = tid + 256 * j;
            const float* cp_ = cbh + ((c >> 2) * 64 + (c & 3));
            float s = 0.f;
#pragma unroll
            for (int e = 0; e < Edim; e++) s += yv[e] * cp_[e * 4];
            bool p1 = s > v1;
            bool p2 = s > v2;
            i2 = p1 ? i1 : (p2 ? c : i2);
            v2 = p1 ? v1 : (p2 ? s : v2);
            i1 = p1 ? c : i1;
            v1 = p1 ? s : v1;
        }
#pragma unroll
        for (int o = 16; o; o >>= 1) {
            float o1 = __shfl_xor_sync(0xffffffffu, v1, o);
            int   oi1 = __shfl_xor_sync(0xffffffffu, i1, o);
            float o2 = __shfl_xor_sync(0xffffffffu, v2, o);
            int   oi2 = __shfl_xor_sync(0xffffffffu, i2, o);
            if (betterf(o1, oi1, v1, i1)) {
                bool k = betterf(v1, i1, o2, oi2);
                v2 = k ? v1 : o2; i2 = k ? i1 : oi2;
                v1 = o1; i1 = oi1;
            } else {
                bool k = betterf(o1, oi1, v2, i2);
                v2 = k ? o1 : v2; i2 = k ? oi1 : i2;
            }
        }
        if (lane == 0) { wv1s[warp] = v1; wi1s[warp] = i1; wv2s[warp] = v2; wi2s[warp] = i2; }
        __syncthreads();
        if (tid == 0) {
            float b1 = wv1s[0], b2 = wv2s[0];
            int   c1 = wi1s[0], c2 = wi2s[0];
#pragma unroll
            for (int w = 1; w < 8; w++) {
                float o1 = wv1s[w], o2 = wv2s[w];
                int  oi1 = wi1s[w], oi2 = wi2s[w];
                if (betterf(o1, oi1, b1, c1)) {
                    bool k = betterf(b1, c1, o2, oi2);
                    b2 = k ? b1 : o2; c2 = k ? c1 : oi2;
                    b1 = o1; c1 = oi1;
                } else {
                    bool k = betterf(o1, oi1, b2, c2);
                    b2 = k ? o1 : b2; c2 = k ? oi1 : c2;
                }
            }
            cands[0] = c1; cands[1] = c2;
        }

        // ---- PB: fp64 mean + projections (coalesced W columns) ----
        const float* xr = x + (size_t)row * Ddim;
        double s = 0.0;
#pragma unroll
        for (int i = 0; i < 4; i++) s += (double)xr[tid + 256 * i];
        redd[tid] = s;
        __syncthreads();
        for (int off = 128; off; off >>= 1) {
            if (tid < off) redd[tid] += redd[tid + off];
            __syncthreads();
        }
        double mu = redd[0] * (1.0 / 1024.0);

        {
            int e0 = 2 * warp, e1 = e0 + 1;
            const float* w0p = g_WtT + (size_t)(h * Edim + e0) * Ddim;
            const float* w1p = g_WtT + (size_t)(h * Edim + e1) * Ddim;
            double a0 = 0.0, a1 = 0.0, sw0 = 0.0, sw1 = 0.0;
            for (int i = 0; i < 32; i++) {
                int d = lane + 32 * i;
                double xd = (double)xr[d];
                double w0 = (double)w0p[d];
                double w1 = (double)w1p[d];
                a0 += xd * w0;  sw0 += w0;
                a1 += xd * w1;  sw1 += w1;
            }
#pragma unroll
            for (int o = 16; o; o >>= 1) {
                a0  += __shfl_xor_sync(0xffffffffu, a0, o);
                a1  += __shfl_xor_sync(0xffffffffu, a1, o);
                sw0 += __shfl_xor_sync(0xffffffffu, sw0, o);
                sw1 += __shfl_xor_sync(0xffffffffu, sw1, o);
            }
            if (lane == 0) {
                spd[e0] = a0 - mu * sw0;
                spd[e1] = a1 - mu * sw1;
            }
        }
        __syncthreads();

        // ---- PC: fp64 verdict between the two candidates ----
        if (warp == 0) {
            int ca = cands[0], cb = cands[1];
            int myc = (lane < 16) ? ca : cb;
            int e = lane & 15;
            double v = spd[e] * g_cbd[((size_t)h * CSdim + myc) * Edim + e];
#pragma unroll
            for (int o = 1; o < 16; o <<= 1)
                v += __shfl_xor_sync(0xffffffffu, v, o);
            double dotA = __shfl_sync(0xffffffffu, v, 0);
            double dotB = __shfl_sync(0xffffffffu, v, 16);
            if (lane == 0) {
                int winner = (dotB > dotA || (dotB == dotA && cb < ca)) ? cb : ca;
                out[(size_t)row * Hdim + h] = (float)winner;
            }
        }
        __syncthreads();
    }
}

// ---------------- launch ------------------------------------------------------
extern "C" void kernel_launch(void* const* d_in, const int* in_sizes, int n_in,
                              void* d_out, int out_size) {
    const float* x   = (const float*)d_in[0];
    const float* W   = (n_in > 1) ? (const float*)d_in[1] : nullptr;
    const float* cbk = (n_in > 2) ? (const float*)d_in[2] : nullptr;
    for (int i = 0; i < n_in; i++) {
        if      (in_sizes[i] == Rdim * Ddim)         x   = (const float*)d_in[i];
        else if (in_sizes[i] == Hdim * Ddim * Edim)  W   = (const float*)d_in[i];
        else if (in_sizes[i] == Hdim * CSdim * Edim) cbk = (const float*)d_in[i];
    }
    float* out = (float*)d_out;   // [4,2048,8] indices stored as float32

    kPrepA<<<576, 256>>>(W, cbk);     // launch 1
    kernY<<<Rdim / 64, 256>>>(x);     // launch 2

    dim3 gs(Rdim / 32, Hdim);         // 256 x 8 = 2048 CTAs (32 rows each)
    kernS<<<gs, 256>>>(out);          // launch 3

    kFix<<<2048, 256>>>(x, out);      // launch 4  <- profiled slot
}

// round 15
// speedup vs baseline: 1.1317x; 1.1317x over previous
#include <cuda_runtime.h>
#include <stdint.h>
#include <math.h>

#define Bdim 4
#define Ndim 2048
#define Ddim 1024
#define Hdim 8
#define Edim 16
#define CSdim 2048
#define Rdim (Bdim*Ndim)   /* 8192 rows */
#define Jdim (Hdim*Edim)   /* 128 projection outputs per row */

// Borderline threshold: flag (row,head) where top-2 gap <= TAU * ||y||.
#define TAU 3e-5f

// ---------------- device scratch (no allocations allowed) ----------------
__device__ float  g_Wt[Ddim*Jdim];            // transposed projs [d][j]  (512KB)
__device__ float  g_WtT[Jdim*Ddim];           // column-major projs [j][d] (512KB, for kFix)
__device__ float  g_cb4[Hdim*CSdim*Edim];     // fp32 normalized codebook, 4-code interleaved (512KB)
__device__ double g_cbd[Hdim*CSdim*Edim];     // fp64 normalized codebook [h][c][e] (2MB)
__device__ float  g_Y[Rdim*Jdim];             // projections after mean-subtract (4MB)
__device__ int    g_list[Rdim*Hdim];          // compact worklist of borderline cases
__device__ int    g_cnt;                      // worklist counter

typedef unsigned long long u64;

__device__ __forceinline__ u64 pack2(float lo, float hi) {
    u64 r; asm("mov.b64 %0,{%1,%2};" : "=l"(r) : "f"(lo), "f"(hi)); return r;
}
__device__ __forceinline__ void unpack2(float& lo, float& hi, u64 v) {
    asm("mov.b64 {%0,%1},%2;" : "=f"(lo), "=f"(hi) : "l"(v));
}
__device__ __forceinline__ u64 ffma2(u64 a, u64 b, u64 c) {
    u64 d; asm("fma.rn.f32x2 %0,%1,%2,%3;" : "=l"(d) : "l"(a), "l"(b), "l"(c)); return d;
}
__device__ __forceinline__ u64 fadd2(u64 a, u64 b) {
    u64 d; asm("add.rn.f32x2 %0,%1,%2;" : "=l"(d) : "l"(a), "l"(b)); return d;
}
__device__ __forceinline__ bool betterf(float av, int ai, float bv, int bi) {
    return (av > bv) || (av == bv && ai < bi);
}

// ---------------- prep A: transposes of W + codebook normalize (fp32 & fp64) --
__global__ void kPrepA(const float* __restrict__ W, const float* __restrict__ cbk) {
    if (blockIdx.x == 0 && threadIdx.x == 0) g_cnt = 0;
    if (blockIdx.x < 512) {
        int idx = blockIdx.x * 256 + threadIdx.x;
        int d = idx >> 7, j = idx & 127;
        float v = W[(j >> 4) * (Ddim * Edim) + d * Edim + (j & 15)];
        g_Wt[idx] = v;
        g_WtT[j * Ddim + d] = v;
    } else {
        int idx = (blockIdx.x - 512) * 256 + threadIdx.x;
        const float* row = cbk + (size_t)idx * Edim;
        float v[Edim];
        double ss = 0.0;
#pragma unroll
        for (int e = 0; e < Edim; e++) { v[e] = row[e]; ss += (double)v[e] * (double)v[e]; }
        double invd = 1.0 / sqrt(ss + 1e-12);
        float inv = (float)invd;
        int h = idx >> 11, c = idx & 2047;
        float* dst = g_cb4 + (size_t)h * (CSdim * Edim) + (c >> 2) * 64 + (c & 3);
        double* dd = g_cbd + (size_t)idx * Edim;
#pragma unroll
        for (int e = 0; e < Edim; e++) {
            dst[e * 4] = v[e] * inv;
            dd[e] = (double)v[e] * invd;
        }
    }
}

// ---------------- kernel Y: Y = X @ Wt - mu * S (64x128 tile, dbl-buffered) ---
__global__ __launch_bounds__(256) void kernY(const float* __restrict__ x) {
    __shared__ __align__(16) float Xs[16][68];
    __shared__ __align__(16) float Wsm[16][128];
    __shared__ float Ssm[128];
    __shared__ float redsum[256];
    __shared__ float mus[64];

    int tid = threadIdx.x;
    int row0 = blockIdx.x * 64;

    int tx = tid & 15, ty = tid >> 4;
    int ldr = tid >> 2, ldc = (tid & 3) * 4;
    int wr  = tid >> 4, wc  = (tid & 15) * 8;

    u64 acc[4][4];
#pragma unroll
    for (int i = 0; i < 4; i++)
#pragma unroll
        for (int p = 0; p < 4; p++) acc[i][p] = 0ull;

    float psum = 0.f;
    float s8[8] = {0.f,0.f,0.f,0.f,0.f,0.f,0.f,0.f};

    float4 xv  = *(const float4*)(x + (size_t)(row0 + ldr) * Ddim + ldc);
    float4 wv0 = *(const float4*)(g_Wt + (size_t)wr * Jdim + wc);
    float4 wv1 = *(const float4*)(g_Wt + (size_t)wr * Jdim + wc + 4);

    for (int kc = 0; kc < Ddim / 16; kc++) {
        psum += xv.x + xv.y + xv.z + xv.w;
        s8[0] += wv0.x; s8[1] += wv0.y; s8[2] += wv0.z; s8[3] += wv0.w;
        s8[4] += wv1.x; s8[5] += wv1.y; s8[6] += wv1.z; s8[7] += wv1.w;
        Xs[ldc + 0][ldr] = xv.x;
        Xs[ldc + 1][ldr] = xv.y;
        Xs[ldc + 2][ldr] = xv.z;
        Xs[ldc + 3][ldr] = xv.w;
        *(float4*)&Wsm[wr][wc]     = wv0;
        *(float4*)&Wsm[wr][wc + 4] = wv1;
        __syncthreads();

        float4 nxv = xv, nwv0 = wv0, nwv1 = wv1;
        if (kc < Ddim / 16 - 1) {
            int k0 = (kc + 1) * 16;
            nxv  = *(const float4*)(x + (size_t)(row0 + ldr) * Ddim + k0 + ldc);
            nwv0 = *(const float4*)(g_Wt + (size_t)(k0 + wr) * Jdim + wc);
            nwv1 = *(const float4*)(g_Wt + (size_t)(k0 + wr) * Jdim + wc + 4);
        }

#pragma unroll
        for (int k = 0; k < 16; k++) {
            float4 av = *(const float4*)&Xs[k][ty * 4];
            u64 a0 = pack2(av.x, av.x);
            u64 a1 = pack2(av.y, av.y);
            u64 a2 = pack2(av.z, av.z);
            u64 a3 = pack2(av.w, av.w);
#pragma unroll
            for (int p = 0; p < 4; p++) {
                u64 b = *(const u64*)&Wsm[k][p * 32 + tx * 2];
                acc[0][p] = ffma2(a0, b, acc[0][p]);
                acc[1][p] = ffma2(a1, b, acc[1][p]);
                acc[2][p] = ffma2(a2, b, acc[2][p]);
                acc[3][p] = ffma2(a3, b, acc[3][p]);
            }
        }
        __syncthreads();
        xv = nxv; wv0 = nwv0; wv1 = nwv1;
    }

    redsum[tid] = psum;
#pragma unroll
    for (int i = 0; i < 4; i++) Wsm[wr][wc + i]     = s8[i];
#pragma unroll
    for (int i = 0; i < 4; i++) Wsm[wr][wc + 4 + i] = s8[4 + i];
    __syncthreads();
    if (tid < 64)
        mus[tid] = (redsum[4 * tid] + redsum[4 * tid + 1] +
                    redsum[4 * tid + 2] + redsum[4 * tid + 3]) * (1.0f / Ddim);
    if (tid < 128) {
        float t = 0.f;
#pragma unroll
        for (int r16 = 0; r16 < 16; r16++) t += Wsm[r16][tid];
        Ssm[tid] = t;
    }
    __syncthreads();

#pragma unroll
    for (int i = 0; i < 4; i++) {
        int r = row0 + ty * 4 + i;
        float mu = mus[ty * 4 + i];
#pragma unroll
        for (int p = 0; p < 4; p++) {
            int n0 = p * 32 + tx * 2;
            float lo, hi;
            unpack2(lo, hi, acc[i][p]);
            lo -= mu * Ssm[n0];
            hi -= mu * Ssm[n0 + 1];
            *(float2*)(g_Y + (size_t)r * Jdim + n0) = make_float2(lo, hi);
        }
    }
}

// ---------------- kernel S: FFMA2 sims, 4-code LDS128 tiles, top-2 argmax -----
// (R12 version: 2 rows/lane, 64-row CTA -- best measured balance: one broadcast
//  LDS128 feeds 4 ffma2.)
__global__ __launch_bounds__(256, 2) void kernS(float* __restrict__ out) {
    __shared__ __align__(16) float buf[2][4096];
    __shared__ float sv1[8][32][2];
    __shared__ float sv2[8][32][2];
    __shared__ int   six[8][32][2];

    int tid = threadIdx.x;
    int lane = tid & 31, warp = tid >> 5;
    int h = blockIdx.y;
    int row0 = blockIdx.x * 64;
    int r0 = row0 + 2 * lane;

    u64 y2[2][Edim];
    float ynorm[2];
#pragma unroll
    for (int rr = 0; rr < 2; rr++) {
        const float* yp = g_Y + (size_t)(r0 + rr) * Jdim + h * Edim;
        float n2 = 0.f;
#pragma unroll
        for (int e4 = 0; e4 < 4; e4++) {
            float4 v = *(const float4*)(yp + e4 * 4);
            n2 += v.x*v.x + v.y*v.y + v.z*v.z + v.w*v.w;
            y2[rr][e4 * 4 + 0] = pack2(v.x, v.x);
            y2[rr][e4 * 4 + 1] = pack2(v.y, v.y);
            y2[rr][e4 * 4 + 2] = pack2(v.z, v.z);
            y2[rr][e4 * 4 + 3] = pack2(v.w, v.w);
        }
        ynorm[rr] = sqrtf(n2);
    }

    const float NEGINF = __int_as_float(0xff800000u);
    float v1_0 = NEGINF, v2_0 = NEGINF, v1_1 = NEGINF, v2_1 = NEGINF;
    int bi0 = 0, bi1 = 0;

    const float4* src = (const float4*)(g_cb4 + (size_t)h * (CSdim * Edim));

#pragma unroll
    for (int i = 0; i < 4; i++)
        ((float4*)buf[0])[tid + 256 * i] = src[tid + 256 * i];
    __syncthreads();

    for (int ch = 0; ch < 8; ch++) {
        int pb = ch & 1;
        float4 pf0, pf1, pf2, pf3;
        if (ch < 7) {
            const float4* s2 = src + (ch + 1) * 1024;
            pf0 = s2[tid];       pf1 = s2[tid + 256];
            pf2 = s2[tid + 512]; pf3 = s2[tid + 768];
        }

        const float* cbp = buf[pb] + warp * (8 * 64);
        int cbase = (ch * 64 + warp * 8) * 4;

#pragma unroll 2
        for (int t = 0; t < 8; t++) {
            u64 aA0 = 0ull, aA1 = 0ull, aB0 = 0ull, aB1 = 0ull;
            u64 bA0 = 0ull, bA1 = 0ull, bB0 = 0ull, bB1 = 0ull;
            const float* cq = cbp + t * 64;
#pragma unroll
            for (int e = 0; e < 8; e++) {
                longlong2 bb = *(const longlong2*)(cq + e * 4);
                u64 c01 = (u64)bb.x, c23 = (u64)bb.y;
                aA0 = ffma2(y2[0][e], c01, aA0);
                aB0 = ffma2(y2[0][e], c23, aB0);
                aA1 = ffma2(y2[1][e], c01, aA1);
                aB1 = ffma2(y2[1][e], c23, aB1);
            }
#pragma unroll
            for (int e = 8; e < 16; e++) {
                longlong2 bb = *(const longlong2*)(cq + e * 4);
                u64 c01 = (u64)bb.x, c23 = (u64)bb.y;
                bA0 = ffma2(y2[0][e], c01, bA0);
                bB0 = ffma2(y2[0][e], c23, bB0);
                bA1 = ffma2(y2[1][e], c01, bA1);
                bB1 = ffma2(y2[1][e], c23, bB1);
            }
            u64 sA0 = fadd2(aA0, bA0), sB0 = fadd2(aB0, bB0);
            u64 sA1 = fadd2(aA1, bA1), sB1 = fadd2(aB1, bB1);
            int c0 = cbase + t * 4;
            float s0, s1, s2, s3, m;
            unpack2(s0, s1, sA0); unpack2(s2, s3, sB0);
            bi0 = (s0 > v1_0) ? c0     : bi0; m = fminf(v1_0, s0); v1_0 = fmaxf(v1_0, s0); v2_0 = fmaxf(v2_0, m);
            bi0 = (s1 > v1_0) ? c0 + 1 : bi0; m = fminf(v1_0, s1); v1_0 = fmaxf(v1_0, s1); v2_0 = fmaxf(v2_0, m);
            bi0 = (s2 > v1_0) ? c0 + 2 : bi0; m = fminf(v1_0, s2); v1_0 = fmaxf(v1_0, s2); v2_0 = fmaxf(v2_0, m);
            bi0 = (s3 > v1_0) ? c0 + 3 : bi0; m = fminf(v1_0, s3); v1_0 = fmaxf(v1_0, s3); v2_0 = fmaxf(v2_0, m);
            unpack2(s0, s1, sA1); unpack2(s2, s3, sB1);
            bi1 = (s0 > v1_1) ? c0     : bi1; m = fminf(v1_1, s0); v1_1 = fmaxf(v1_1, s0); v2_1 = fmaxf(v2_1, m);
            bi1 = (s1 > v1_1) ? c0 + 1 : bi1; m = fminf(v1_1, s1); v1_1 = fmaxf(v1_1, s1); v2_1 = fmaxf(v2_1, m);
            bi1 = (s2 > v1_1) ? c0 + 2 : bi1; m = fminf(v1_1, s2); v1_1 = fmaxf(v1_1, s2); v2_1 = fmaxf(v2_1, m);
            bi1 = (s3 > v1_1) ? c0 + 3 : bi1; m = fminf(v1_1, s3); v1_1 = fmaxf(v1_1, s3); v2_1 = fmaxf(v2_1, m);
        }

        __syncthreads();
        if (ch < 7) {
            float4* d2 = (float4*)buf[pb ^ 1];
            d2[tid] = pf0;       d2[tid + 256] = pf1;
            d2[tid + 512] = pf2; d2[tid + 768] = pf3;
            __syncthreads();
        }
    }

    sv1[warp][lane][0] = v1_0; sv1[warp][lane][1] = v1_1;
    sv2[warp][lane][0] = v2_0; sv2[warp][lane][1] = v2_1;
    six[warp][lane][0] = bi0;  six[warp][lane][1] = bi1;
    __syncthreads();

    if (warp == 0) {
#pragma unroll
        for (int rr = 0; rr < 2; rr++) {
            float v1 = NEGINF, v2 = NEGINF;
            int i1 = 0;
#pragma unroll
            for (int w = 0; w < 8; w++) {
                float a = sv1[w][lane][rr];
                int  ia = six[w][lane][rr];
                float b = sv2[w][lane][rr];
                if (a > v1 || (a == v1 && ia < i1)) {
                    v2 = fmaxf(v2, v1); v1 = a; i1 = ia;
                } else {
                    v2 = fmaxf(v2, a);
                }
                v2 = fmaxf(v2, b);
            }
            int id = (r0 + rr) * Hdim + h;
            out[id] = (float)i1;
            if (v1 - v2 <= TAU * ynorm[rr]) {
                int slot = atomicAdd(&g_cnt, 1);
                g_list[slot] = id;
            }
        }
    }
}

// ---------------- kernel Fix: candidate top-2 (fp32) + fp64 verdict -----------
__global__ __launch_bounds__(256) void kFix(const float* __restrict__ x,
                                            float* __restrict__ out) {
    __shared__ float  syf[Edim];
    __shared__ float  wv1s[8], wv2s[8];
    __shared__ int    wi1s[8], wi2s[8];
    __shared__ double redd[256];
    __shared__ double spd[Edim];
    __shared__ int    cands[2];

    int tid = threadIdx.x;
    int lane = tid & 31, warp = tid >> 5;
    int cnt = g_cnt;

    for (int item = blockIdx.x; item < cnt; item += 2048) {
        int wid = g_list[item];
        int row = wid >> 3, h = wid & 7;

        // ---- PA: fp32 re-rank from g_Y -> top-2 candidate codes ----
        if (tid < Edim) syf[tid] = g_Y[(size_t)row * Jdim + h * Edim + tid];
        __syncthreads();
        float yv[Edim];
#pragma unroll
        for (int e = 0; e < Edim; e++) yv[e] = syf[e];

        const float* cbh = g_cb4 + (size_t)h * (CSdim * Edim);
        const float NEGINF = __int_as_float(0xff800000u);
        float v1 = NEGINF, v2 = NEGINF;
        int i1 = 0, i2 = 1;
#pragma unroll
        for (int j = 0; j < 8; j++) {
            int c = tid + 256 * j;
            const float* cp_ = cbh + ((c >> 2) * 64 + (c & 3));
            float s = 0.f;
#pragma unroll
            for (int e = 0; e < Edim; e++) s += yv[e] * cp_[e * 4];
            bool p1 = s > v1;
            bool p2 = s > v2;
            i2 = p1 ? i1 : (p2 ? c : i2);
            v2 = p1 ? v1 : (p2 ? s : v2);
            i1 = p1 ? c : i1;
            v1 = p1 ? s : v1;
        }
#pragma unroll
        for (int o = 16; o; o >>= 1) {
            float o1 = __shfl_xor_sync(0xffffffffu, v1, o);
            int   oi1 = __shfl_xor_sync(0xffffffffu, i1, o);
            float o2 = __shfl_xor_sync(0xffffffffu, v2, o);
            int   oi2 = __shfl_xor_sync(0xffffffffu, i2, o);
            if (betterf(o1, oi1, v1, i1)) {
                bool k = betterf(v1, i1, o2, oi2);
                v2 = k ? v1 : o2; i2 = k ? i1 : oi2;
                v1 = o1; i1 = oi1;
            } else {
                bool k = betterf(o1, oi1, v2, i2);
                v2 = k ? o1 : v2; i2 = k ? oi1 : i2;
            }
        }
        if (lane == 0) { wv1s[warp] = v1; wi1s[warp] = i1; wv2s[warp] = v2; wi2s[warp] = i2; }
        __syncthreads();
        if (tid == 0) {
            float b1 = wv1s[0], b2 = wv2s[0];
            int   c1 = wi1s[0], c2 = wi2s[0];
#pragma unroll
            for (int w = 1; w < 8; w++) {
                float o1 = wv1s[w], o2 = wv2s[w];
                int  oi1 = wi1s[w], oi2 = wi2s[w];
                if (betterf(o1, oi1, b1, c1)) {
                    bool k = betterf(b1, c1, o2, oi2);
                    b2 = k ? b1 : o2; c2 = k ? c1 : oi2;
                    b1 = o1; c1 = oi1;
                } else {
                    bool k = betterf(o1, oi1, b2, c2);
                    b2 = k ? o1 : b2; c2 = k ? oi1 : c2;
                }
            }
            cands[0] = c1; cands[1] = c2;
        }

        // ---- PB: fp64 mean + projections (coalesced W columns) ----
        const float* xr = x + (size_t)row * Ddim;
        double s = 0.0;
#pragma unroll
        for (int i = 0; i < 4; i++) s += (double)xr[tid + 256 * i];
        redd[tid] = s;
        __syncthreads();
        for (int off = 128; off; off >>= 1) {
            if (tid < off) redd[tid] += redd[tid + off];
            __syncthreads();
        }
        double mu = redd[0] * (1.0 / 1024.0);

        {
            int e0 = 2 * warp, e1 = e0 + 1;
            const float* w0p = g_WtT + (size_t)(h * Edim + e0) * Ddim;
            const float* w1p = g_WtT + (size_t)(h * Edim + e1) * Ddim;
            double a0 = 0.0, a1 = 0.0, sw0 = 0.0, sw1 = 0.0;
            for (int i = 0; i < 32; i++) {
                int d = lane + 32 * i;
                double xd = (double)xr[d];
                double w0 = (double)w0p[d];
                double w1 = (double)w1p[d];
                a0 += xd * w0;  sw0 += w0;
                a1 += xd * w1;  sw1 += w1;
            }
#pragma unroll
            for (int o = 16; o; o >>= 1) {
                a0  += __shfl_xor_sync(0xffffffffu, a0, o);
                a1  += __shfl_xor_sync(0xffffffffu, a1, o);
                sw0 += __shfl_xor_sync(0xffffffffu, sw0, o);
                sw1 += __shfl_xor_sync(0xffffffffu, sw1, o);
            }
            if (lane == 0) {
                spd[e0] = a0 - mu * sw0;
                spd[e1] = a1 - mu * sw1;
            }
        }
        __syncthreads();

        // ---- PC: fp64 verdict between the two candidates ----
        if (warp == 0) {
            int ca = cands[0], cb = cands[1];
            int myc = (lane < 16) ? ca : cb;
            int e = lane & 15;
            double v = spd[e] * g_cbd[((size_t)h * CSdim + myc) * Edim + e];
#pragma unroll
            for (int o = 1; o < 16; o <<= 1)
                v += __shfl_xor_sync(0xffffffffu, v, o);
            double dotA = __shfl_sync(0xffffffffu, v, 0);
            double dotB = __shfl_sync(0xffffffffu, v, 16);
            if (lane == 0) {
                int winner = (dotB > dotA || (dotB == dotA && cb < ca)) ? cb : ca;
                out[(size_t)row * Hdim + h] = (float)winner;
            }
        }
        __syncthreads();
    }
}

// ---------------- launch ------------------------------------------------------
extern "C" void kernel_launch(void* const* d_in, const int* in_sizes, int n_in,
                              void* d_out, int out_size) {
    const float* x   = (const float*)d_in[0];
    const float* W   = (n_in > 1) ? (const float*)d_in[1] : nullptr;
    const float* cbk = (n_in > 2) ? (const float*)d_in[2] : nullptr;
    for (int i = 0; i < n_in; i++) {
        if      (in_sizes[i] == Rdim * Ddim)         x   = (const float*)d_in[i];
        else if (in_sizes[i] == Hdim * Ddim * Edim)  W   = (const float*)d_in[i];
        else if (in_sizes[i] == Hdim * CSdim * Edim) cbk = (const float*)d_in[i];
    }
    float* out = (float*)d_out;   // [4,2048,8] indices stored as float32

    kPrepA<<<576, 256>>>(W, cbk);     // launch 1
    kernY<<<Rdim / 64, 256>>>(x);     // launch 2

    dim3 gs(Rdim / 64, Hdim);         // 128 x 8 CTAs (64 rows each)
    kernS<<<gs, 256>>>(out);          // launch 3

    kFix<<<2048, 256>>>(x, out);      // launch 4  <- profiled slot
}